// round 1
// baseline (speedup 1.0000x reference)
#include <cuda_runtime.h>
#include <cuda_bf16.h>

// Conv: inputs (32,64,64,128) NHWC fp32, w (256, 3*3*128) [(kh,kw,c) order],
// bias (256). VALID 3x3 stride 1 -> out (32,62,62,256) fp32.
// Implicit GEMM: M = 32*62*62 = 123008 (= 1922*64 exactly), N = 256, K = 1152.

#define N_IMG 32
#define H_IN 64
#define W_IN 64
#define C_IN 128
#define F_OUT 256
#define HO 62
#define WO 62
#define KDIM 1152   // 9 * 128

#define BM 64
#define BN 64
#define BK 32
#define TM 4
#define TN 8
// threads = (BM/TM)*(BN/TN) = 16*8 = 128

__global__ __launch_bounds__(128)
void conv2d_igemm_fp32(const float* __restrict__ in,
                       const float* __restrict__ w,
                       const float* __restrict__ bias,
                       float* __restrict__ out) {
    __shared__ float As[BM][BK + 1];
    __shared__ float Bs[BN][BK + 1];

    const int tid = threadIdx.x;
    const int m_base = blockIdx.x * BM;   // 0..1921 tiles
    const int f_base = blockIdx.y * BN;   // 0..3 tiles

    // Compute-thread coords: 16 threads along M, 8 along N
    const int mt = tid >> 3;              // 0..15
    const int nt = tid & 7;               // 0..7
    const int m0 = mt * TM;               // row offset in tile
    const int n0 = nt * TN;               // col offset in tile

    // Load coords: each thread loads 4 rows (lrow + 16*r), 4 consecutive floats
    const int lrow = tid >> 3;            // 0..15
    const int lcol = (tid & 7) * 4;       // 0,4,...,28

    // Per-loaded-row input base offset (kh=kw=0, c=0): ((n*64+ho)*64+wo)*128
    int arow_base[4];
#pragma unroll
    for (int r = 0; r < 4; r++) {
        int m   = m_base + lrow + r * 16;
        int n   = m / (HO * WO);
        int rem = m - n * (HO * WO);
        int ho  = rem / WO;
        int wo  = rem - ho * WO;
        arow_base[r] = ((n * H_IN + ho) * W_IN + wo) * C_IN;
    }

    float acc[TM][TN];
#pragma unroll
    for (int i = 0; i < TM; i++)
#pragma unroll
        for (int j = 0; j < TN; j++) acc[i][j] = 0.0f;

    for (int p = 0; p < 9; p++) {
        const int kh = p / 3, kw = p - kh * 3;
        const int in_off = (kh * W_IN + kw) * C_IN;   // shift within input image
        const int wk_off = p * C_IN;                   // offset in K dim of w

        for (int c0 = 0; c0 < C_IN; c0 += BK) {
            // ---- load A tile (64 pixels x 32 channels), float4 coalesced ----
#pragma unroll
            for (int r = 0; r < 4; r++) {
                const float4 v = *reinterpret_cast<const float4*>(
                    in + arow_base[r] + in_off + c0 + lcol);
                const int row = lrow + r * 16;
                As[row][lcol + 0] = v.x;
                As[row][lcol + 1] = v.y;
                As[row][lcol + 2] = v.z;
                As[row][lcol + 3] = v.w;
            }
            // ---- load B tile (64 filters x 32 k), float4 along K ----
#pragma unroll
            for (int r = 0; r < 4; r++) {
                const int row = lrow + r * 16;
                const int f   = f_base + row;
                const float4 v = *reinterpret_cast<const float4*>(
                    w + (long)f * KDIM + wk_off + c0 + lcol);
                Bs[row][lcol + 0] = v.x;
                Bs[row][lcol + 1] = v.y;
                Bs[row][lcol + 2] = v.z;
                Bs[row][lcol + 3] = v.w;
            }
            __syncthreads();

            // ---- compute ----
#pragma unroll
            for (int kk = 0; kk < BK; kk++) {
                float a[TM], bv[TN];
#pragma unroll
                for (int i = 0; i < TM; i++) a[i] = As[m0 + i][kk];
#pragma unroll
                for (int j = 0; j < TN; j++) bv[j] = Bs[n0 + j][kk];
#pragma unroll
                for (int i = 0; i < TM; i++)
#pragma unroll
                    for (int j = 0; j < TN; j++)
                        acc[i][j] = fmaf(a[i], bv[j], acc[i][j]);
            }
            __syncthreads();
        }
    }

    // ---- epilogue: add bias, vectorized stores (TN=8 contiguous filters) ----
    const int f0 = f_base + n0;
    float4 b_lo = *reinterpret_cast<const float4*>(bias + f0);
    float4 b_hi = *reinterpret_cast<const float4*>(bias + f0 + 4);
#pragma unroll
    for (int i = 0; i < TM; i++) {
        const long m = m_base + m0 + i;
        float4 o0, o1;
        o0.x = acc[i][0] + b_lo.x; o0.y = acc[i][1] + b_lo.y;
        o0.z = acc[i][2] + b_lo.z; o0.w = acc[i][3] + b_lo.w;
        o1.x = acc[i][4] + b_hi.x; o1.y = acc[i][5] + b_hi.y;
        o1.z = acc[i][6] + b_hi.z; o1.w = acc[i][7] + b_hi.w;
        *reinterpret_cast<float4*>(out + m * F_OUT + f0)     = o0;
        *reinterpret_cast<float4*>(out + m * F_OUT + f0 + 4) = o1;
    }
}

extern "C" void kernel_launch(void* const* d_in, const int* in_sizes, int n_in,
                              void* d_out, int out_size) {
    const float* in   = (const float*)d_in[0];   // (32,64,64,128)
    const float* w    = (const float*)d_in[1];   // (256,1152)
    const float* bias = (const float*)d_in[2];   // (256,)
    float* out        = (float*)d_out;           // (32,62,62,256)

    dim3 grid((N_IMG * HO * WO) / BM, F_OUT / BN);  // (1922, 4)
    conv2d_igemm_fp32<<<grid, 128>>>(in, w, bias, out);
}

// round 3
// speedup vs baseline: 2.6357x; 2.6357x over previous
#include <cuda_runtime.h>
#include <cuda_bf16.h>
#include <cstdint>

// Conv (32,64,64,128) NHWC fp32 * w(256,1152) + b -> out (32,62,62,256) fp32.
// Implicit GEMM on mma.sync bf16 (x3 split for fp32-grade accuracy):
//   D = Ah*Bh + Ah*Bl + Al*Bh   (bf16 hi/lo decomposition, fp32 accumulate)
// M = 123008 = 961*128, N = 256, K = 1152 = 36 chunks of 32.
// Pre-pass kernels split fp32 -> bf16 hi/lo into __device__ scratch.

#define H_IN 64
#define W_IN 64
#define C_IN 128
#define F_OUT 256
#define HO 62
#define WO 62
#define KDIM 1152
#define BM 128
#define BN 256
#define NCHUNK 36
#define STAGES 4
#define THREADS 256

#define A_BYTES (BM * 64)                  // 8192 per split (128 rows x 32 bf16)
#define B_BYTES (BN * 64)                  // 16384 per split
#define OFF_AH 0
#define OFF_AL (A_BYTES)
#define OFF_BH (2 * A_BYTES)
#define OFF_BL (2 * A_BYTES + B_BYTES)
#define STAGE_SZ (2 * A_BYTES + 2 * B_BYTES)   // 49152
#define SMEM_TOTAL (STAGES * STAGE_SZ)         // 196608

#define IN_ELEMS (32 * 64 * 64 * 128)
#define W_ELEMS (F_OUT * KDIM)

__device__ __align__(16) __nv_bfloat16 g_inHi[IN_ELEMS];
__device__ __align__(16) __nv_bfloat16 g_inLo[IN_ELEMS];
__device__ __align__(16) __nv_bfloat16 g_wHi[W_ELEMS];
__device__ __align__(16) __nv_bfloat16 g_wLo[W_ELEMS];

// ---------------- helpers ----------------
__device__ __forceinline__ uint32_t smem_u32(const void* p) {
    uint32_t a;
    asm("{ .reg .u64 t; cvta.to.shared.u64 t, %1; cvt.u32.u64 %0, t; }"
        : "=r"(a) : "l"(p));
    return a;
}

__device__ __forceinline__ void cpa16(uint32_t dst, const void* src) {
    asm volatile("cp.async.cg.shared.global [%0], [%1], 16;"
                 :: "r"(dst), "l"(src));
}
#define CP_COMMIT() asm volatile("cp.async.commit_group;" ::: "memory")
#define CP_WAIT2()  asm volatile("cp.async.wait_group 2;" ::: "memory")
#define CP_WAIT0()  asm volatile("cp.async.wait_group 0;" ::: "memory")

__device__ __forceinline__ void ldm4(uint32_t* r, uint32_t a) {
    asm volatile("ldmatrix.sync.aligned.m8n8.x4.shared.b16 {%0,%1,%2,%3}, [%4];"
                 : "=r"(r[0]), "=r"(r[1]), "=r"(r[2]), "=r"(r[3]) : "r"(a));
}

__device__ __forceinline__ void mma16816(float* c, const uint32_t* a,
                                         uint32_t b0, uint32_t b1) {
    asm volatile(
        "mma.sync.aligned.m16n8k16.row.col.f32.bf16.bf16.f32 "
        "{%0,%1,%2,%3}, {%4,%5,%6,%7}, {%8,%9}, {%0,%1,%2,%3};"
        : "+f"(c[0]), "+f"(c[1]), "+f"(c[2]), "+f"(c[3])
        : "r"(a[0]), "r"(a[1]), "r"(a[2]), "r"(a[3]), "r"(b0), "r"(b1));
}

__device__ __forceinline__ void split4v(float4 v, uint2& hv, uint2& lv) {
    float f[4] = {v.x, v.y, v.z, v.w};
    unsigned hb[4], lb[4];
#pragma unroll
    for (int i = 0; i < 4; i++) {
        __nv_bfloat16 h = __float2bfloat16(f[i]);
        float r = f[i] - __bfloat162float(h);
        __nv_bfloat16 l = __float2bfloat16(r);
        hb[i] = (unsigned)__bfloat16_as_ushort(h);
        lb[i] = (unsigned)__bfloat16_as_ushort(l);
    }
    hv.x = hb[0] | (hb[1] << 16); hv.y = hb[2] | (hb[3] << 16);
    lv.x = lb[0] | (lb[1] << 16); lv.y = lb[2] | (lb[3] << 16);
}

// ---------------- pre-pass: fp32 -> bf16 hi/lo ----------------
__global__ void split_input(const float4* __restrict__ src) {
    const int n4 = IN_ELEMS / 4;
    const int stride = gridDim.x * blockDim.x;
    uint2* h = reinterpret_cast<uint2*>(g_inHi);
    uint2* l = reinterpret_cast<uint2*>(g_inLo);
    for (int i = blockIdx.x * blockDim.x + threadIdx.x; i < n4; i += stride) {
        uint2 hv, lv; split4v(src[i], hv, lv);
        h[i] = hv; l[i] = lv;
    }
}

__global__ void split_weights(const float4* __restrict__ src) {
    const int n4 = W_ELEMS / 4;
    const int stride = gridDim.x * blockDim.x;
    uint2* h = reinterpret_cast<uint2*>(g_wHi);
    uint2* l = reinterpret_cast<uint2*>(g_wLo);
    for (int i = blockIdx.x * blockDim.x + threadIdx.x; i < n4; i += stride) {
        uint2 hv, lv; split4v(src[i], hv, lv);
        h[i] = hv; l[i] = lv;
    }
}

// ---------------- main GEMM ----------------
// smem swizzle: within a 64B row of 4x16B chunks, chunk c -> c ^ ((row>>1)&3).
__device__ __forceinline__ void prefetch_stage(uint32_t sb, int stage, int ch,
                                               long arow, int tid) {
    const int p  = ch >> 2;                 // filter tap 0..8
    const int c0 = (ch & 3) * 32;           // channel offset within tap
    const int kh = p / 3, kw = p - kh * 3;
    const long in_off = (long)(kh * W_IN + kw) * C_IN + c0;
    const int k0 = ch * 32;
    const uint32_t st = sb + stage * STAGE_SZ;

    // A: 128 rows x 32 ch; thread pair per row; 2x16B per split per thread
    {
        const int row = tid >> 1;
        const __nv_bfloat16* sh = g_inHi + arow + in_off;
        const __nv_bfloat16* sl = g_inLo + arow + in_off;
#pragma unroll
        for (int j = 0; j < 2; j++) {
            const int c  = (tid & 1) * 2 + j;
            const int cs = c ^ ((row >> 1) & 3);
            const uint32_t off = row * 64 + cs * 16;
            cpa16(st + OFF_AH + off, sh + c * 8);
            cpa16(st + OFF_AL + off, sl + c * 8);
        }
    }
    // B: 256 filter rows x 32 k; one row per thread; 4x16B per split
    {
        const __nv_bfloat16* sh = g_wHi + (long)tid * KDIM + k0;
        const __nv_bfloat16* sl = g_wLo + (long)tid * KDIM + k0;
#pragma unroll
        for (int c = 0; c < 4; c++) {
            const int cs = c ^ ((tid >> 1) & 3);
            const uint32_t off = tid * 64 + cs * 16;
            cpa16(st + OFF_BH + off, sh + c * 8);
            cpa16(st + OFF_BL + off, sl + c * 8);
        }
    }
}

__global__ __launch_bounds__(THREADS, 1)
void conv_gemm_hmma(const float* __restrict__ bias, float* __restrict__ out) {
    extern __shared__ char smem[];
    const uint32_t sb = smem_u32(smem);
    const int tid  = threadIdx.x;
    const int lane = tid & 31;
    const int wid  = tid >> 5;
    const int warpM = wid >> 2;    // 0..1 -> 64-row slab
    const int warpN = wid & 3;     // 0..3 -> 64-col slab
    const int m_base = blockIdx.x * BM;

    // gmem base of this thread's A row (row index = tid>>1 in tile)
    const int m_ar = m_base + (tid >> 1);
    const int nimg = m_ar / (HO * WO);
    const int rem  = m_ar - nimg * (HO * WO);
    const int ho   = rem / WO;
    const int wo   = rem - ho * WO;
    const long arow = ((long)(nimg * H_IN + ho) * W_IN + wo) * C_IN;

    float acc[4][8][4];
#pragma unroll
    for (int i = 0; i < 4; i++)
#pragma unroll
        for (int j = 0; j < 8; j++)
#pragma unroll
            for (int k = 0; k < 4; k++) acc[i][j][k] = 0.0f;

    // pipeline prologue: fill STAGES-1 stages
#pragma unroll
    for (int s = 0; s < STAGES - 1; s++) {
        prefetch_stage(sb, s, s, arow, tid);
        CP_COMMIT();
    }

    for (int ch = 0; ch < NCHUNK; ch++) {
        CP_WAIT2();
        __syncthreads();   // stage (ch) visible to all; stage (ch-1) free

        const int pf = ch + STAGES - 1;
        if (pf < NCHUNK) prefetch_stage(sb, pf & 3, pf, arow, tid);
        CP_COMMIT();

        const uint32_t st = sb + (ch & 3) * STAGE_SZ;
#pragma unroll
        for (int s = 0; s < 2; s++) {          // two k16 steps per 32-chunk
            uint32_t ah[4][4], al[4][4], bh[4][4], bl[4][4];
#pragma unroll
            for (int mb = 0; mb < 4; mb++) {
                const int row = warpM * 64 + mb * 16 + (lane & 15);
                const int c   = s * 2 + (lane >> 4);
                const int cs  = c ^ ((row >> 1) & 3);
                const uint32_t off = row * 64 + cs * 16;
                ldm4(ah[mb], st + OFF_AH + off);
                ldm4(al[mb], st + OFF_AL + off);
            }
#pragma unroll
            for (int nb = 0; nb < 4; nb++) {
                const int row = warpN * 64 + nb * 16 + (lane & 15);
                const int c   = s * 2 + (lane >> 4);
                const int cs  = c ^ ((row >> 1) & 3);
                const uint32_t off = row * 64 + cs * 16;
                ldm4(bh[nb], st + OFF_BH + off);
                ldm4(bl[nb], st + OFF_BL + off);
            }
#pragma unroll
            for (int mb = 0; mb < 4; mb++)
#pragma unroll
                for (int nb = 0; nb < 4; nb++)
#pragma unroll
                    for (int h = 0; h < 2; h++) {
                        float* c = acc[mb][nb * 2 + h];
                        mma16816(c, ah[mb], bh[nb][h], bh[nb][h + 2]);
                        mma16816(c, ah[mb], bl[nb][h], bl[nb][h + 2]);
                        mma16816(c, al[mb], bh[nb][h], bh[nb][h + 2]);
                    }
        }
    }
    CP_WAIT0();

    // ---- epilogue: bias + fp32 stores (float2 per fragment row) ----
#pragma unroll
    for (int nb = 0; nb < 8; nb++) {
        const int n = warpN * 64 + nb * 8 + (lane & 3) * 2;
        const float2 bv = *reinterpret_cast<const float2*>(bias + n);
#pragma unroll
        for (int mb = 0; mb < 4; mb++) {
            const long m0 = (long)m_base + warpM * 64 + mb * 16 + (lane >> 2);
            const float* c = acc[mb][nb];
            float2 v0, v1;
            v0.x = c[0] + bv.x; v0.y = c[1] + bv.y;
            v1.x = c[2] + bv.x; v1.y = c[3] + bv.y;
            *reinterpret_cast<float2*>(out + m0 * F_OUT + n)       = v0;
            *reinterpret_cast<float2*>(out + (m0 + 8) * F_OUT + n) = v1;
        }
    }
}

extern "C" void kernel_launch(void* const* d_in, const int* in_sizes, int n_in,
                              void* d_out, int out_size) {
    const float* in   = (const float*)d_in[0];
    const float* w    = (const float*)d_in[1];
    const float* bias = (const float*)d_in[2];
    float* out        = (float*)d_out;

    split_input<<<4096, 256>>>((const float4*)in);
    split_weights<<<288, 256>>>((const float4*)w);

    cudaFuncSetAttribute(conv_gemm_hmma,
                         cudaFuncAttributeMaxDynamicSharedMemorySize, SMEM_TOTAL);
    conv_gemm_hmma<<<961, THREADS, SMEM_TOTAL>>>(bias, out);
}

// round 4
// speedup vs baseline: 6.1532x; 2.3345x over previous
#include <cuda_runtime.h>
#include <cuda_fp16.h>
#include <cstdint>

// Conv (32,64,64,128) NHWC fp32 * w(256,1152) + b -> out (32,62,62,256) fp32.
// Implicit GEMM on mma.sync m16n8k16 fp16 (fp32 accumulate), single pass.
// M = 123008 = 961*128, N = 256, K = 1152 = 36 chunks of 32.
// Pre-pass converts fp32 -> fp16 into __device__ scratch.

#define H_IN 64
#define W_IN 64
#define C_IN 128
#define F_OUT 256
#define HO 62
#define WO 62
#define KDIM 1152
#define BM 128
#define BN 256
#define NCHUNK 36
#define STAGES 4
#define THREADS 256

#define A_BYTES (BM * 64)                  // 8192  (128 rows x 32 fp16)
#define B_BYTES (BN * 64)                  // 16384 (256 rows x 32 fp16)
#define OFF_A 0
#define OFF_B (A_BYTES)
#define STAGE_SZ (A_BYTES + B_BYTES)       // 24576
#define SMEM_TOTAL (STAGES * STAGE_SZ)     // 98304

#define IN_ELEMS (32 * 64 * 64 * 128)
#define W_ELEMS (F_OUT * KDIM)

__device__ __align__(16) __half g_inH[IN_ELEMS];
__device__ __align__(16) __half g_wH[W_ELEMS];

// ---------------- helpers ----------------
__device__ __forceinline__ uint32_t smem_u32(const void* p) {
    uint32_t a;
    asm("{ .reg .u64 t; cvta.to.shared.u64 t, %1; cvt.u32.u64 %0, t; }"
        : "=r"(a) : "l"(p));
    return a;
}

__device__ __forceinline__ void cpa16(uint32_t dst, const void* src) {
    asm volatile("cp.async.cg.shared.global [%0], [%1], 16;"
                 :: "r"(dst), "l"(src));
}
#define CP_COMMIT() asm volatile("cp.async.commit_group;" ::: "memory")
#define CP_WAIT2()  asm volatile("cp.async.wait_group 2;" ::: "memory")
#define CP_WAIT0()  asm volatile("cp.async.wait_group 0;" ::: "memory")

__device__ __forceinline__ void ldm4(uint32_t* r, uint32_t a) {
    asm volatile("ldmatrix.sync.aligned.m8n8.x4.shared.b16 {%0,%1,%2,%3}, [%4];"
                 : "=r"(r[0]), "=r"(r[1]), "=r"(r[2]), "=r"(r[3]) : "r"(a));
}

__device__ __forceinline__ void mma16816(float* c, const uint32_t* a,
                                         uint32_t b0, uint32_t b1) {
    asm volatile(
        "mma.sync.aligned.m16n8k16.row.col.f32.f16.f16.f32 "
        "{%0,%1,%2,%3}, {%4,%5,%6,%7}, {%8,%9}, {%0,%1,%2,%3};"
        : "+f"(c[0]), "+f"(c[1]), "+f"(c[2]), "+f"(c[3])
        : "r"(a[0]), "r"(a[1]), "r"(a[2]), "r"(a[3]), "r"(b0), "r"(b1));
}

// fp32x4 -> fp16x4 packed into uint2
__device__ __forceinline__ uint2 cvt4(float4 v) {
    __half2 p0 = __floats2half2_rn(v.x, v.y);
    __half2 p1 = __floats2half2_rn(v.z, v.w);
    uint2 r;
    r.x = *reinterpret_cast<uint32_t*>(&p0);
    r.y = *reinterpret_cast<uint32_t*>(&p1);
    return r;
}

// ---------------- pre-pass: fp32 -> fp16 ----------------
__global__ void cvt_input(const float4* __restrict__ src) {
    const int n4 = IN_ELEMS / 4;
    const int stride = gridDim.x * blockDim.x;
    uint2* h = reinterpret_cast<uint2*>(g_inH);
    for (int i = blockIdx.x * blockDim.x + threadIdx.x; i < n4; i += stride)
        h[i] = cvt4(src[i]);
}

__global__ void cvt_weights(const float4* __restrict__ src) {
    const int n4 = W_ELEMS / 4;
    const int stride = gridDim.x * blockDim.x;
    uint2* h = reinterpret_cast<uint2*>(g_wH);
    for (int i = blockIdx.x * blockDim.x + threadIdx.x; i < n4; i += stride)
        h[i] = cvt4(src[i]);
}

// ---------------- main GEMM ----------------
// smem swizzle: within a 64B row of 4x16B chunks, chunk c -> c ^ ((row>>1)&3).
__device__ __forceinline__ void prefetch_stage(uint32_t sb, int stage, int ch,
                                               long arow, int tid) {
    const int p  = ch >> 2;                 // filter tap 0..8
    const int c0 = (ch & 3) * 32;           // channel offset within tap
    const int kh = p / 3, kw = p - kh * 3;
    const long in_off = (long)(kh * W_IN + kw) * C_IN + c0;
    const int k0 = ch * 32;
    const uint32_t st = sb + stage * STAGE_SZ;

    // A: 128 rows x 32 ch; thread pair per row; 2x16B per thread
    {
        const int row = tid >> 1;
        const __half* sh = g_inH + arow + in_off;
#pragma unroll
        for (int j = 0; j < 2; j++) {
            const int c  = (tid & 1) * 2 + j;
            const int cs = c ^ ((row >> 1) & 3);
            cpa16(st + OFF_A + row * 64 + cs * 16, sh + c * 8);
        }
    }
    // B: 256 filter rows x 32 k; one row per thread; 4x16B
    {
        const __half* sh = g_wH + (long)tid * KDIM + k0;
#pragma unroll
        for (int c = 0; c < 4; c++) {
            const int cs = c ^ ((tid >> 1) & 3);
            cpa16(st + OFF_B + tid * 64 + cs * 16, sh + c * 8);
        }
    }
}

__global__ __launch_bounds__(THREADS, 1)
void conv_gemm_hmma(const float* __restrict__ bias, float* __restrict__ out) {
    extern __shared__ char smem[];
    const uint32_t sb = smem_u32(smem);
    const int tid  = threadIdx.x;
    const int lane = tid & 31;
    const int wid  = tid >> 5;
    const int warpM = wid >> 2;    // 0..1 -> 64-row slab
    const int warpN = wid & 3;     // 0..3 -> 64-col slab
    const int m_base = blockIdx.x * BM;

    // gmem base of this thread's A row (row index = tid>>1 in tile)
    const int m_ar = m_base + (tid >> 1);
    const int nimg = m_ar / (HO * WO);
    const int rem  = m_ar - nimg * (HO * WO);
    const int ho   = rem / WO;
    const int wo   = rem - ho * WO;
    const long arow = ((long)(nimg * H_IN + ho) * W_IN + wo) * C_IN;

    float acc[4][8][4];
#pragma unroll
    for (int i = 0; i < 4; i++)
#pragma unroll
        for (int j = 0; j < 8; j++)
#pragma unroll
            for (int k = 0; k < 4; k++) acc[i][j][k] = 0.0f;

    // pipeline prologue: fill STAGES-1 stages
#pragma unroll
    for (int s = 0; s < STAGES - 1; s++) {
        prefetch_stage(sb, s, s, arow, tid);
        CP_COMMIT();
    }

    for (int ch = 0; ch < NCHUNK; ch++) {
        CP_WAIT2();
        __syncthreads();   // stage (ch) visible; stage (ch-1) free for refill

        const int pf = ch + STAGES - 1;
        if (pf < NCHUNK) prefetch_stage(sb, pf & 3, pf, arow, tid);
        CP_COMMIT();

        const uint32_t st = sb + (ch & 3) * STAGE_SZ;
#pragma unroll
        for (int s = 0; s < 2; s++) {          // two k16 steps per 32-chunk
            uint32_t ah[4][4], bh[4][4];
#pragma unroll
            for (int mb = 0; mb < 4; mb++) {
                const int row = warpM * 64 + mb * 16 + (lane & 15);
                const int c   = s * 2 + (lane >> 4);
                const int cs  = c ^ ((row >> 1) & 3);
                ldm4(ah[mb], st + OFF_A + row * 64 + cs * 16);
            }
#pragma unroll
            for (int nb = 0; nb < 4; nb++) {
                const int row = warpN * 64 + nb * 16 + (lane & 15);
                const int c   = s * 2 + (lane >> 4);
                const int cs  = c ^ ((row >> 1) & 3);
                ldm4(bh[nb], st + OFF_B + row * 64 + cs * 16);
            }
#pragma unroll
            for (int mb = 0; mb < 4; mb++)
#pragma unroll
                for (int nb = 0; nb < 4; nb++)
#pragma unroll
                    for (int h = 0; h < 2; h++)
                        mma16816(acc[mb][nb * 2 + h], ah[mb],
                                 bh[nb][h], bh[nb][h + 2]);
        }
    }
    CP_WAIT0();

    // ---- epilogue: bias + fp32 stores (float2 per fragment row) ----
#pragma unroll
    for (int nb = 0; nb < 8; nb++) {
        const int n = warpN * 64 + nb * 8 + (lane & 3) * 2;
        const float2 bv = *reinterpret_cast<const float2*>(bias + n);
#pragma unroll
        for (int mb = 0; mb < 4; mb++) {
            const long m0 = (long)m_base + warpM * 64 + mb * 16 + (lane >> 2);
            const float* c = acc[mb][nb];
            float2 v0, v1;
            v0.x = c[0] + bv.x; v0.y = c[1] + bv.y;
            v1.x = c[2] + bv.x; v1.y = c[3] + bv.y;
            *reinterpret_cast<float2*>(out + m0 * F_OUT + n)       = v0;
            *reinterpret_cast<float2*>(out + (m0 + 8) * F_OUT + n) = v1;
        }
    }
}

extern "C" void kernel_launch(void* const* d_in, const int* in_sizes, int n_in,
                              void* d_out, int out_size) {
    const float* in   = (const float*)d_in[0];
    const float* w    = (const float*)d_in[1];
    const float* bias = (const float*)d_in[2];
    float* out        = (float*)d_out;

    cvt_input<<<4096, 256>>>((const float4*)in);
    cvt_weights<<<288, 256>>>((const float4*)w);

    cudaFuncSetAttribute(conv_gemm_hmma,
                         cudaFuncAttributeMaxDynamicSharedMemorySize, SMEM_TOTAL);
    conv_gemm_hmma<<<961, THREADS, SMEM_TOTAL>>>(bias, out);
}

// round 5
// speedup vs baseline: 7.9046x; 1.2846x over previous
#include <cuda_runtime.h>
#include <cuda_fp16.h>
#include <cstdint>

// Conv (32,64,64,128) NHWC fp32 * w(256,1152) + b -> out (32,62,62,256) fp32.
// Implicit GEMM on mma.sync m16n8k16 fp16 (fp32 accumulate).
// M = 123008 = 961*128, N = 256 (2 CTA tiles of 128), K = 1152 = 18 chunks of 64.
// 2 CTAs/SM resident (96KB smem, <=128 regs) for latency hiding.

#define H_IN 64
#define W_IN 64
#define C_IN 128
#define F_OUT 256
#define HO 62
#define WO 62
#define KDIM 1152
#define BM 128
#define BN 128
#define CK 64
#define NCHUNK 18
#define STAGES 3
#define THREADS 256

#define A_BYTES (BM * CK * 2)              // 16384
#define B_BYTES (BN * CK * 2)              // 16384
#define OFF_A 0
#define OFF_B (A_BYTES)
#define STAGE_SZ (A_BYTES + B_BYTES)       // 32768
#define SMEM_TOTAL (STAGES * STAGE_SZ)     // 98304

#define IN_ELEMS (32 * 64 * 64 * 128)
#define W_ELEMS (F_OUT * KDIM)

__device__ __align__(16) __half g_inH[IN_ELEMS];
__device__ __align__(16) __half g_wH[W_ELEMS];

// ---------------- helpers ----------------
__device__ __forceinline__ uint32_t smem_u32(const void* p) {
    uint32_t a;
    asm("{ .reg .u64 t; cvta.to.shared.u64 t, %1; cvt.u32.u64 %0, t; }"
        : "=r"(a) : "l"(p));
    return a;
}

__device__ __forceinline__ void cpa16(uint32_t dst, const void* src) {
    asm volatile("cp.async.cg.shared.global [%0], [%1], 16;"
                 :: "r"(dst), "l"(src));
}
#define CP_COMMIT() asm volatile("cp.async.commit_group;" ::: "memory")
#define CP_WAIT1()  asm volatile("cp.async.wait_group 1;" ::: "memory")
#define CP_WAIT0()  asm volatile("cp.async.wait_group 0;" ::: "memory")

__device__ __forceinline__ void ldm4(uint32_t* r, uint32_t a) {
    asm volatile("ldmatrix.sync.aligned.m8n8.x4.shared.b16 {%0,%1,%2,%3}, [%4];"
                 : "=r"(r[0]), "=r"(r[1]), "=r"(r[2]), "=r"(r[3]) : "r"(a));
}

__device__ __forceinline__ void mma16816(float* c, const uint32_t* a,
                                         uint32_t b0, uint32_t b1) {
    asm volatile(
        "mma.sync.aligned.m16n8k16.row.col.f32.f16.f16.f32 "
        "{%0,%1,%2,%3}, {%4,%5,%6,%7}, {%8,%9}, {%0,%1,%2,%3};"
        : "+f"(c[0]), "+f"(c[1]), "+f"(c[2]), "+f"(c[3])
        : "r"(a[0]), "r"(a[1]), "r"(a[2]), "r"(a[3]), "r"(b0), "r"(b1));
}

__device__ __forceinline__ uint2 cvt4(float4 v) {
    __half2 p0 = __floats2half2_rn(v.x, v.y);
    __half2 p1 = __floats2half2_rn(v.z, v.w);
    uint2 r;
    r.x = *reinterpret_cast<uint32_t*>(&p0);
    r.y = *reinterpret_cast<uint32_t*>(&p1);
    return r;
}

// ---------------- pre-pass: fp32 -> fp16 ----------------
__global__ void cvt_input(const float4* __restrict__ src) {
    const int n4 = IN_ELEMS / 4;
    const int stride = gridDim.x * blockDim.x;
    uint2* h = reinterpret_cast<uint2*>(g_inH);
    for (int i = blockIdx.x * blockDim.x + threadIdx.x; i < n4; i += stride)
        h[i] = cvt4(src[i]);
}

__global__ void cvt_weights(const float4* __restrict__ src) {
    const int n4 = W_ELEMS / 4;
    const int stride = gridDim.x * blockDim.x;
    uint2* h = reinterpret_cast<uint2*>(g_wH);
    for (int i = blockIdx.x * blockDim.x + threadIdx.x; i < n4; i += stride)
        h[i] = cvt4(src[i]);
}

// ---------------- main GEMM ----------------
// Rows are 128B = 8 x 16B chunks; swizzle: chunk c -> c ^ (row & 7).
__device__ __forceinline__ void prefetch_stage(uint32_t sb, int stage, int ch,
                                               const __half* aptr,
                                               const __half* bptr, int tid) {
    // aptr = g_inH + arow (tap 0 base for this thread's row)
    // bptr = g_wH + f*KDIM (this thread's filter row)
    const int p     = ch >> 1;              // filter tap 0..8
    const int chalf = (ch & 1) * 64;        // channel offset within tap
    const int kh = p / 3, kw = p - kh * 3;
    const long a_off = (long)(kh * W_IN + kw) * C_IN + chalf;
    const int  k0    = ch * CK;
    const uint32_t st = sb + stage * STAGE_SZ;

    const int row = tid >> 1;
    const int h   = tid & 1;
#pragma unroll
    for (int j = 0; j < 4; j++) {
        const int c  = h * 4 + j;
        const int cs = c ^ (row & 7);
        cpa16(st + OFF_A + row * 128 + cs * 16, aptr + a_off + c * 8);
        cpa16(st + OFF_B + row * 128 + cs * 16, bptr + k0 + c * 8);
    }
}

__global__ __launch_bounds__(THREADS, 2)
void conv_gemm_hmma(const float* __restrict__ bias, float* __restrict__ out) {
    extern __shared__ char smem[];
    const uint32_t sb = smem_u32(smem);
    const int tid  = threadIdx.x;
    const int lane = tid & 31;
    const int wid  = tid >> 5;
    const int warpM = wid >> 2;    // 0..1 -> 64-row slab
    const int warpN = wid & 3;     // 0..3 -> 32-col slab
    const int m_base = blockIdx.x * BM;
    const int n_base = blockIdx.y * BN;

    // gmem base of this thread's A row (tile row = tid>>1)
    const int m_ar = m_base + (tid >> 1);
    const int nimg = m_ar / (HO * WO);
    const int rem  = m_ar - nimg * (HO * WO);
    const int ho   = rem / WO;
    const int wo   = rem - ho * WO;
    const __half* aptr = g_inH + ((long)(nimg * H_IN + ho) * W_IN + wo) * C_IN;
    const __half* bptr = g_wH + (long)(n_base + (tid >> 1)) * KDIM;

    float acc[4][4][4];
#pragma unroll
    for (int i = 0; i < 4; i++)
#pragma unroll
        for (int j = 0; j < 4; j++)
#pragma unroll
            for (int k = 0; k < 4; k++) acc[i][j][k] = 0.0f;

    // prologue: fill STAGES-1 = 2 stages
#pragma unroll
    for (int s = 0; s < STAGES - 1; s++) {
        prefetch_stage(sb, s, s, aptr, bptr, tid);
        CP_COMMIT();
    }

    int stage = 0;
    for (int ch = 0; ch < NCHUNK; ch++) {
        CP_WAIT1();
        __syncthreads();   // stage (ch) data visible; previous stage free

        const int pf = ch + STAGES - 1;
        int pstage = stage + STAGES - 1; if (pstage >= STAGES) pstage -= STAGES;
        if (pf < NCHUNK) prefetch_stage(sb, pstage, pf, aptr, bptr, tid);
        CP_COMMIT();

        const uint32_t st = sb + stage * STAGE_SZ;
#pragma unroll
        for (int s = 0; s < 4; s++) {          // four k16 steps per 64-chunk
            uint32_t ah[4][4], bh[2][4];
#pragma unroll
            for (int mb = 0; mb < 4; mb++) {
                const int row = warpM * 64 + mb * 16 + (lane & 15);
                const int c   = s * 2 + (lane >> 4);
                const int cs  = c ^ (row & 7);
                ldm4(ah[mb], st + OFF_A + row * 128 + cs * 16);
            }
#pragma unroll
            for (int i = 0; i < 2; i++) {
                const int row = warpN * 32 + i * 16 + (lane & 15);
                const int c   = s * 2 + (lane >> 4);
                const int cs  = c ^ (row & 7);
                ldm4(bh[i], st + OFF_B + row * 128 + cs * 16);
            }
#pragma unroll
            for (int mb = 0; mb < 4; mb++)
#pragma unroll
                for (int i = 0; i < 2; i++)
#pragma unroll
                    for (int h = 0; h < 2; h++)
                        mma16816(acc[mb][i * 2 + h], ah[mb],
                                 bh[i][h], bh[i][h + 2]);
        }
        stage++; if (stage == STAGES) stage = 0;
    }
    CP_WAIT0();

    // ---- epilogue: bias + fp32 stores ----
#pragma unroll
    for (int nb = 0; nb < 4; nb++) {
        const int n = n_base + warpN * 32 + nb * 8 + (lane & 3) * 2;
        const float2 bv = *reinterpret_cast<const float2*>(bias + n);
#pragma unroll
        for (int mb = 0; mb < 4; mb++) {
            const long m0 = (long)m_base + warpM * 64 + mb * 16 + (lane >> 2);
            const float* c = acc[mb][nb];
            float2 v0, v1;
            v0.x = c[0] + bv.x; v0.y = c[1] + bv.y;
            v1.x = c[2] + bv.x; v1.y = c[3] + bv.y;
            *reinterpret_cast<float2*>(out + m0 * F_OUT + n)       = v0;
            *reinterpret_cast<float2*>(out + (m0 + 8) * F_OUT + n) = v1;
        }
    }
}

extern "C" void kernel_launch(void* const* d_in, const int* in_sizes, int n_in,
                              void* d_out, int out_size) {
    const float* in   = (const float*)d_in[0];
    const float* w    = (const float*)d_in[1];
    const float* bias = (const float*)d_in[2];
    float* out        = (float*)d_out;

    cvt_input<<<4096, 256>>>((const float4*)in);
    cvt_weights<<<288, 256>>>((const float4*)w);

    cudaFuncSetAttribute(conv_gemm_hmma,
                         cudaFuncAttributeMaxDynamicSharedMemorySize, SMEM_TOTAL);
    dim3 grid(961, 2);
    conv_gemm_hmma<<<grid, THREADS, SMEM_TOTAL>>>(bias, out);
}